// round 8
// baseline (speedup 1.0000x reference)
#include <cuda_runtime.h>
#include <cuda_bf16.h>
#include <cstdint>

#define NN 20000
#define DIN 128
#define HIDC 128
#define NHEADS 4
#define MAXM (NHEADS * HIDC)      // 512
#define EMAX 320000
#define ETOTMAX (EMAX + NN)

// -------------------- scratch (device globals) ------------------------------
__device__ float         g_h1 [NN * MAXM];
__device__ float         g_h2 [NN * MAXM];
__device__ __nv_bfloat16 g_xlh[NN * MAXM];
__device__ float         g_as [3 * NN * NHEADS];
__device__ float         g_ad [3 * NN * NHEADS];
__device__ float         g_pool[HIDC];
__device__ int           g_csr_src[ETOTMAX];
__device__ int           g_row_ptr[NN + 1];
__device__ int           g_cnt[NN];
__device__ int           g_cursor[NN];

// -------------------- helpers ----------------------------------------------
__device__ __forceinline__ uint32_t cvt_tf32(float f) {
    uint32_t o;
    asm volatile("cvt.rna.tf32.f32 %0, %1;" : "=r"(o) : "f"(f));
    return o;
}
__device__ __forceinline__ uint32_t smem_u32(const void* p) {
    return (uint32_t)__cvta_generic_to_shared(p);
}
__device__ __forceinline__ void cp16(uint32_t saddr, const float* g, int srcsz) {
    asm volatile("cp.async.cg.shared.global [%0], [%1], 16, %2;"
                 :: "r"(saddr), "l"(g), "r"(srcsz));
}
__device__ __forceinline__ void cp_commit() {
    asm volatile("cp.async.commit_group;");
}
__device__ __forceinline__ void cp_wait1() {
    asm volatile("cp.async.wait_group 1;");
}
__device__ __forceinline__ void edge_sd(const int* __restrict__ ei, int E, int e,
                                        int& s, int& d) {
    if (e < E) { s = ei[e]; d = ei[E + e]; }
    else       { s = d = e - E; }
}

// ==================== init (cnt, as/ad x3, pool) ============================
__global__ void k_init(int* cnt, float* as, float* ad, float* pool, int n) {
    int i = blockIdx.x * blockDim.x + threadIdx.x;
    if (i < n) cnt[i] = 0;
    int tot = 3 * n * NHEADS;
    if (i < tot) { as[i] = 0.f; ad[i] = 0.f; }
    if (i < HIDC) pool[i] = 0.f;
}

// ==================== CSR build =============================================
__global__ void k_count(const int* __restrict__ ei, int E, int Etot,
                        int* __restrict__ cnt) {
    int e = blockIdx.x * blockDim.x + threadIdx.x;
    if (e >= Etot) return;
    int s, d; edge_sd(ei, E, e, s, d);
    atomicAdd(&cnt[d], 1);
}
__global__ void k_scan(const int* __restrict__ cnt, int* __restrict__ row_ptr,
                       int* __restrict__ cursor, int n) {
    __shared__ int part[1024];
    int t = threadIdx.x;
    int per = (n + 1023) / 1024;
    int begi = t * per;
    int endi = min(n, begi + per);
    int s = 0;
    for (int i = begi; i < endi; i++) s += cnt[i];
    part[t] = s;
    __syncthreads();
    for (int o = 1; o < 1024; o <<= 1) {
        int v = (t >= o) ? part[t - o] : 0;
        __syncthreads();
        part[t] += v;
        __syncthreads();
    }
    int off = t ? part[t - 1] : 0;
    for (int i = begi; i < endi; i++) {
        row_ptr[i] = off; cursor[i] = off;
        off += cnt[i];
    }
    if (t == 1023) row_ptr[n] = part[1023];
}
__global__ void k_scatter(const int* __restrict__ ei, int E, int Etot,
                          int* __restrict__ cursor, int* __restrict__ csr_src) {
    int e = blockIdx.x * blockDim.x + threadIdx.x;
    if (e >= Etot) return;
    int s, d; edge_sd(ei, E, e, s, d);
    int pos = atomicAdd(&cursor[d], 1);
    csr_src[pos] = s;
}

// ==================== cp.async 3-stage tf32 GEMM + attn-dot epilogue ========
// C = A[n,K] @ B[K,M]; bf16 xl store + fused attention partial dots.
#define BM 128
#define BN 64
#define BK 16
#define STAGES 3

__device__ __forceinline__ void mma_tf32(float* c, const uint32_t* a, const uint32_t* b) {
    asm volatile(
        "mma.sync.aligned.m16n8k8.row.col.f32.tf32.tf32.f32 "
        "{%0,%1,%2,%3}, {%4,%5,%6,%7}, {%8,%9}, {%0,%1,%2,%3};"
        : "+f"(c[0]), "+f"(c[1]), "+f"(c[2]), "+f"(c[3])
        : "r"(a[0]), "r"(a[1]), "r"(a[2]), "r"(a[3]), "r"(b[0]), "r"(b[1]));
}

__global__ __launch_bounds__(256, 3) void k_gemm_fused(
    const float* __restrict__ A, const float* __restrict__ B,
    const float* __restrict__ a_s, const float* __restrict__ a_d,
    __nv_bfloat16* __restrict__ xlh,
    float* __restrict__ as, float* __restrict__ ad,
    int n, int K, int M, int H) {
    __shared__ float As[STAGES][BM][BK + 4];   // f32, [m][k]
    __shared__ float Bs[STAGES][BK][BN + 8];   // f32, [k][n]
    int tid = threadIdx.x;
    int warp = tid >> 5, lane = tid & 31;
    int gid = lane >> 2, tig = lane & 3;
    int warpM = warp & 3, warpN = warp >> 2;
    int row0 = blockIdx.y * BM, col0 = blockIdx.x * BN;

    float c[2][4][4] = {};

    // copy assignments
    int a_r = tid >> 1;            // 0..127
    int a_c = (tid & 1) * 8;       // 0 or 8
    int b_r = tid >> 4;            // 0..15
    int b_c = (tid & 15) * 4;      // n-col

    int grow_a = row0 + a_r;
    int a_sz = (grow_a < n) ? 16 : 0;

    auto issue = [&](int kt, int st) {
        const float* gA = A + (size_t)grow_a * K + kt + a_c;
        uint32_t sA = smem_u32(&As[st][a_r][a_c]);
        cp16(sA,      gA,     a_sz);
        cp16(sA + 16, gA + 4, a_sz);
        const float* gB = B + (size_t)(kt + b_r) * M + col0 + b_c;
        cp16(smem_u32(&Bs[st][b_r][b_c]), gB, 16);
    };

    auto compute = [&](int st) {
#pragma unroll
        for (int kk = 0; kk < BK; kk += 8) {
            uint32_t afr[2][4];
#pragma unroll
            for (int t = 0; t < 2; t++) {
                int m = warpM * 32 + t * 16 + gid;
                afr[t][0] = cvt_tf32(As[st][m][kk + tig]);
                afr[t][1] = cvt_tf32(As[st][m + 8][kk + tig]);
                afr[t][2] = cvt_tf32(As[st][m][kk + tig + 4]);
                afr[t][3] = cvt_tf32(As[st][m + 8][kk + tig + 4]);
            }
            uint32_t bfr[4][2];
#pragma unroll
            for (int t = 0; t < 4; t++) {
                int nn2 = warpN * 32 + t * 8 + gid;
                bfr[t][0] = cvt_tf32(Bs[st][kk + tig][nn2]);
                bfr[t][1] = cvt_tf32(Bs[st][kk + tig + 4][nn2]);
            }
#pragma unroll
            for (int i = 0; i < 2; i++)
#pragma unroll
                for (int j = 0; j < 4; j++)
                    mma_tf32(c[i][j], afr[i], bfr[j]);
        }
    };

    int KT = K / BK;
    issue(0, 0);  cp_commit();
    issue(BK, 1); cp_commit();
    int st = 0;
    for (int t = 0; t < KT; t++) {
        cp_wait1();
        __syncthreads();
        int t2 = t + 2;
        if (t2 < KT) issue(t2 * BK, (st + 2) % STAGES);
        cp_commit();
        compute(st);
        st = (st + 1) % STAGES;
        __syncthreads();
    }

    // ---- epilogue: bf16 store + fused attention partial dots ----
    int h = col0 / HIDC;
    int inh0 = col0 - h * HIDC;
    float ws[4][2], wd[4][2];
#pragma unroll
    for (int j = 0; j < 4; j++)
#pragma unroll
        for (int q = 0; q < 2; q++) {
            int cc = inh0 + warpN * 32 + j * 8 + tig * 2 + q;
            ws[j][q] = a_s[h * HIDC + cc];
            wd[j][q] = a_d[h * HIDC + cc];
        }
#pragma unroll
    for (int i = 0; i < 2; i++) {
        int r0 = row0 + warpM * 32 + i * 16 + gid;
        float ps0 = 0.f, pd0 = 0.f, ps8 = 0.f, pd8 = 0.f;
#pragma unroll
        for (int j = 0; j < 4; j++) {
            ps0 += c[i][j][0] * ws[j][0] + c[i][j][1] * ws[j][1];
            pd0 += c[i][j][0] * wd[j][0] + c[i][j][1] * wd[j][1];
            ps8 += c[i][j][2] * ws[j][0] + c[i][j][3] * ws[j][1];
            pd8 += c[i][j][2] * wd[j][0] + c[i][j][3] * wd[j][1];
            int cc = col0 + warpN * 32 + j * 8 + tig * 2;
            if (r0 < n) {
                __nv_bfloat162 v = __float22bfloat162_rn(make_float2(c[i][j][0], c[i][j][1]));
                *(__nv_bfloat162*)(xlh + (size_t)r0 * M + cc) = v;
            }
            if (r0 + 8 < n) {
                __nv_bfloat162 v = __float22bfloat162_rn(make_float2(c[i][j][2], c[i][j][3]));
                *(__nv_bfloat162*)(xlh + (size_t)(r0 + 8) * M + cc) = v;
            }
        }
#pragma unroll
        for (int o = 1; o < 4; o <<= 1) {
            ps0 += __shfl_xor_sync(0xffffffffu, ps0, o);
            pd0 += __shfl_xor_sync(0xffffffffu, pd0, o);
            ps8 += __shfl_xor_sync(0xffffffffu, ps8, o);
            pd8 += __shfl_xor_sync(0xffffffffu, pd8, o);
        }
        if (tig == 0) {
            if (r0 < n) {
                atomicAdd(&as[r0 * H + h], ps0);
                atomicAdd(&ad[r0 * H + h], pd0);
            }
            if (r0 + 8 < n) {
                atomicAdd(&as[(r0 + 8) * H + h], ps8);
                atomicAdd(&ad[(r0 + 8) * H + h], pd8);
            }
        }
    }
}

// ==================== fused softmax + bf16 gather aggregate =================
// one warp per (node, head); lane handles channels 4*lane..4*lane+3 (uint2 gather)
__global__ void k_node_agg(const int* __restrict__ csr_src,
                           const int* __restrict__ row_ptr,
                           const __nv_bfloat16* __restrict__ xlh,
                           const float* __restrict__ as,
                           const float* __restrict__ ad,
                           const float* __restrict__ b,
                           float* __restrict__ out,
                           int n, int H, int M, int relu) {
    int w = (blockIdx.x * blockDim.x + threadIdx.x) >> 5;
    if (w >= n * H) return;
    int node = w / H, h = w - node * H;
    int lane = threadIdx.x & 31;
    int beg = row_ptr[node], deg = row_ptr[node + 1] - beg;
    float ad_n = ad[node * H + h];

    float m = -3.4e38f;
    for (int i = lane; i < deg; i += 32) {
        int s = csr_src[beg + i];
        float e = as[s * H + h] + ad_n;
        e = e > 0.f ? e : 0.2f * e;
        m = fmaxf(m, e);
    }
#pragma unroll
    for (int o = 16; o; o >>= 1) m = fmaxf(m, __shfl_xor_sync(0xffffffffu, m, o));

    float den = 0.f;
    float a00 = 0.f, a01 = 0.f, a10 = 0.f, a11 = 0.f;
    const uint32_t* xbase = (const uint32_t*)xlh;
    for (int i0 = 0; i0 < deg; i0 += 32) {
        int i = i0 + lane;
        float x = 0.f; int s = 0;
        if (i < deg) {
            s = csr_src[beg + i];
            float e = as[s * H + h] + ad_n;
            e = e > 0.f ? e : 0.2f * e;
            x = __expf(e - m);
            den += x;
        }
        int cnt = min(32, deg - i0);
        for (int j = 0; j < cnt; j++) {
            float xj = __shfl_sync(0xffffffffu, x, j);
            int   sj = __shfl_sync(0xffffffffu, s, j);
            const uint2 u = *(const uint2*)(xbase + (((size_t)sj * M + h * HIDC) >> 1) + 2 * lane);
            a00 += xj * __uint_as_float(u.x << 16);
            a01 += xj * __uint_as_float(u.x & 0xffff0000u);
            a10 += xj * __uint_as_float(u.y << 16);
            a11 += xj * __uint_as_float(u.y & 0xffff0000u);
        }
    }
#pragma unroll
    for (int o = 16; o; o >>= 1) den += __shfl_xor_sync(0xffffffffu, den, o);
    float inv = 1.f / den;

    int c0 = 4 * lane;
    float v0 = a00 * inv + b[h * HIDC + c0];
    float v1 = a01 * inv + b[h * HIDC + c0 + 1];
    float v2 = a10 * inv + b[h * HIDC + c0 + 2];
    float v3 = a11 * inv + b[h * HIDC + c0 + 3];
    if (relu) {
        v0 = fmaxf(v0, 0.f); v1 = fmaxf(v1, 0.f);
        v2 = fmaxf(v2, 0.f); v3 = fmaxf(v3, 0.f);
    }
    float* op = out + (size_t)node * M + h * HIDC;
    *(float4*)(op + c0) = make_float4(v0, v1, v2, v3);
}

// ==================== pool + MLP ============================================
__global__ void k_pool(const float* __restrict__ h, float* __restrict__ pool, int n) {
    int t = threadIdx.x;  // 128
    float s = 0.f;
    for (int r = blockIdx.x; r < n; r += gridDim.x)
        s += h[(size_t)r * HIDC + t];
    atomicAdd(&pool[t], s);
}
__global__ void k_mlp(const float* __restrict__ pool, const float* __restrict__ Wm1,
                      const float* __restrict__ bm1, const float* __restrict__ Wm2,
                      const float* __restrict__ bm2, float* __restrict__ out,
                      float invn) {
    __shared__ float g[HIDC];
    __shared__ float t1[HIDC / 2];
    int t = threadIdx.x;  // 128
    g[t] = pool[t] * invn;
    __syncthreads();
    if (t < HIDC / 2) {
        float s = bm1[t];
#pragma unroll 8
        for (int i = 0; i < HIDC; i++) s += g[i] * Wm1[i * (HIDC / 2) + t];
        t1[t] = fmaxf(s, 0.f);
    }
    __syncthreads();
    if (t == 0) {
        float s = bm2[0];
#pragma unroll 8
        for (int j = 0; j < HIDC / 2; j++) s += t1[j] * Wm2[j];
        out[0] = s;
    }
}

// ============================================================================
extern "C" void kernel_launch(void* const* d_in, const int* in_sizes, int n_in,
                              void* d_out, int out_size) {
    const float* x    = (const float*)d_in[0];
    const int*   ei   = (const int*)  d_in[1];
    const float* W0   = (const float*)d_in[2];
    const float* as0  = (const float*)d_in[3];
    const float* ad0  = (const float*)d_in[4];
    const float* b0   = (const float*)d_in[5];
    const float* W1   = (const float*)d_in[6];
    const float* as1  = (const float*)d_in[7];
    const float* ad1  = (const float*)d_in[8];
    const float* b1   = (const float*)d_in[9];
    const float* W2   = (const float*)d_in[10];
    const float* as2  = (const float*)d_in[11];
    const float* ad2  = (const float*)d_in[12];
    const float* b2   = (const float*)d_in[13];
    const float* Wm1  = (const float*)d_in[14];
    const float* bm1  = (const float*)d_in[15];
    const float* Wm2  = (const float*)d_in[16];
    const float* bm2  = (const float*)d_in[17];

    int n = in_sizes[0] / DIN;        // 20000
    int E = in_sizes[1] / 2;          // 320000
    int Etot = E + n;

    float *h1, *h2, *asb, *adb, *pool;
    __nv_bfloat16* xlh;
    int *csr_src, *row_ptr, *cnt, *cursor;
    { void* p;
      cudaGetSymbolAddress(&p, g_h1);      h1      = (float*)p;
      cudaGetSymbolAddress(&p, g_h2);      h2      = (float*)p;
      cudaGetSymbolAddress(&p, g_xlh);     xlh     = (__nv_bfloat16*)p;
      cudaGetSymbolAddress(&p, g_as);      asb     = (float*)p;
      cudaGetSymbolAddress(&p, g_ad);      adb     = (float*)p;
      cudaGetSymbolAddress(&p, g_pool);    pool    = (float*)p;
      cudaGetSymbolAddress(&p, g_csr_src); csr_src = (int*)p;
      cudaGetSymbolAddress(&p, g_row_ptr); row_ptr = (int*)p;
      cudaGetSymbolAddress(&p, g_cnt);     cnt     = (int*)p;
      cudaGetSymbolAddress(&p, g_cursor);  cursor  = (int*)p;
    }

    int initN = 3 * n * NHEADS;       // 240000 covers everything
    k_init   <<<(initN + 255) / 256, 256>>>(cnt, asb, adb, pool, n);
    k_count  <<<(Etot + 255) / 256, 256>>>(ei, E, Etot, cnt);
    k_scan   <<<1, 1024>>>(cnt, row_ptr, cursor, n);
    k_scatter<<<(Etot + 255) / 256, 256>>>(ei, E, Etot, cursor, csr_src);

    auto run_layer = [&](const float* in, int K, int H, int layer,
                         const float* W, const float* a_s, const float* a_d,
                         const float* b, float* out, int relu) {
        int M = H * HIDC;
        float* asL = asb + (size_t)layer * NN * NHEADS;
        float* adL = adb + (size_t)layer * NN * NHEADS;
        dim3 gg(M / BN, (n + BM - 1) / BM);
        k_gemm_fused<<<gg, 256>>>(in, W, a_s, a_d, xlh, asL, adL, n, K, M, H);
        int warps = n * H;
        k_node_agg<<<(warps * 32 + 255) / 256, 256>>>(csr_src, row_ptr, xlh,
                                                      asL, adL, b, out, n, H, M, relu);
    };

    run_layer(x,  DIN,         NHEADS, 0, W0, as0, ad0, b0, h1, 1);
    run_layer(h1, NHEADS*HIDC, NHEADS, 1, W1, as1, ad1, b1, h2, 1);
    run_layer(h2, NHEADS*HIDC, 1,      2, W2, as2, ad2, b2, h1, 0);

    k_pool<<<256, HIDC>>>(h1, pool, n);
    k_mlp<<<1, HIDC>>>(pool, Wm1, bm1, Wm2, bm2, (float*)d_out, 1.f / (float)n);
}

// round 10
// speedup vs baseline: 1.1846x; 1.1846x over previous
#include <cuda_runtime.h>
#include <cuda_bf16.h>
#include <cstdint>

#define NN 20000
#define DIN 128
#define HIDC 128
#define NHEADS 4
#define MAXM (NHEADS * HIDC)      // 512
#define EMAX 320000
#define ETOTMAX (EMAX + NN)

// -------------------- scratch (device globals) ------------------------------
__device__ float         g_h1 [NN * MAXM];
__device__ float         g_h2 [NN * MAXM];
__device__ __nv_bfloat16 g_xlh[NN * MAXM];
__device__ float         g_as [3 * NN * NHEADS];
__device__ float         g_ad [3 * NN * NHEADS];
__device__ float         g_pool[HIDC];
__device__ int           g_csr_src[ETOTMAX];
__device__ int           g_row_ptr[NN + 1];
__device__ int           g_cnt[NN];
__device__ int           g_cursor[NN];

// -------------------- helpers ----------------------------------------------
__device__ __forceinline__ uint32_t bf2_pack(float lo, float hi) {
    __nv_bfloat162 v = __float22bfloat162_rn(make_float2(lo, hi));
    return *(uint32_t*)&v;
}
__device__ __forceinline__ void edge_sd(const int* __restrict__ ei, int E, int e,
                                        int& s, int& d) {
    if (e < E) { s = ei[e]; d = ei[E + e]; }
    else       { s = d = e - E; }
}

// ==================== init (cnt, as/ad x3, pool) ============================
__global__ void k_init(int* cnt, float* as, float* ad, float* pool, int n) {
    int i = blockIdx.x * blockDim.x + threadIdx.x;
    if (i < n) cnt[i] = 0;
    int tot = 3 * n * NHEADS;
    if (i < tot) { as[i] = 0.f; ad[i] = 0.f; }
    if (i < HIDC) pool[i] = 0.f;
}

// ==================== CSR build =============================================
__global__ void k_count(const int* __restrict__ ei, int E, int Etot,
                        int* __restrict__ cnt) {
    int e = blockIdx.x * blockDim.x + threadIdx.x;
    if (e >= Etot) return;
    int s, d; edge_sd(ei, E, e, s, d);
    atomicAdd(&cnt[d], 1);
}
__global__ void k_scan(const int* __restrict__ cnt, int* __restrict__ row_ptr,
                       int* __restrict__ cursor, int n) {
    __shared__ int part[1024];
    int t = threadIdx.x;
    int per = (n + 1023) / 1024;
    int begi = t * per;
    int endi = min(n, begi + per);
    int s = 0;
    for (int i = begi; i < endi; i++) s += cnt[i];
    part[t] = s;
    __syncthreads();
    for (int o = 1; o < 1024; o <<= 1) {
        int v = (t >= o) ? part[t - o] : 0;
        __syncthreads();
        part[t] += v;
        __syncthreads();
    }
    int off = t ? part[t - 1] : 0;
    for (int i = begi; i < endi; i++) {
        row_ptr[i] = off; cursor[i] = off;
        off += cnt[i];
    }
    if (t == 1023) row_ptr[n] = part[1023];
}
__global__ void k_scatter(const int* __restrict__ ei, int E, int Etot,
                          int* __restrict__ cursor, int* __restrict__ csr_src) {
    int e = blockIdx.x * blockDim.x + threadIdx.x;
    if (e >= Etot) return;
    int s, d; edge_sd(ei, E, e, s, d);
    int pos = atomicAdd(&cursor[d], 1);
    csr_src[pos] = s;
}

// ==================== bf16 tensor-core GEMM + attn-dot epilogue =============
// C = A[n,K] @ B[K,M] via mma.m16n8k16.bf16, fp32 accum.
// BM=128, BN=64, BK=64, 256 threads, single-buffered smem (reg-limited occ).
#define BM 128
#define BN 64
#define BK 64

__device__ __forceinline__ void mma_bf16(float* c, const uint32_t* a, const uint32_t* b) {
    asm volatile(
        "mma.sync.aligned.m16n8k16.row.col.f32.bf16.bf16.f32 "
        "{%0,%1,%2,%3}, {%4,%5,%6,%7}, {%8,%9}, {%0,%1,%2,%3};"
        : "+f"(c[0]), "+f"(c[1]), "+f"(c[2]), "+f"(c[3])
        : "r"(a[0]), "r"(a[1]), "r"(a[2]), "r"(a[3]), "r"(b[0]), "r"(b[1]));
}

__global__ __launch_bounds__(256) void k_gemm_fused(
    const float* __restrict__ A, const float* __restrict__ B,
    const float* __restrict__ a_s, const float* __restrict__ a_d,
    __nv_bfloat16* __restrict__ xlh,
    float* __restrict__ as, float* __restrict__ ad,
    int n, int K, int M, int H) {
    __shared__ __nv_bfloat16 As[BM][BK + 8];   // [m][k], k-pairs u32-aligned
    __shared__ uint32_t      Bs[BK / 2][BN + 8]; // packed k-pairs per n
    int tid = threadIdx.x;
    int warp = tid >> 5, lane = tid & 31;
    int gid = lane >> 2, tig = lane & 3;
    int warpM = warp & 3, warpN = warp >> 2;
    int row0 = blockIdx.y * BM, col0 = blockIdx.x * BN;

    float c[2][4][4] = {};

    int a_r = tid >> 4;            // 0..15, 8 passes of +16
    int a_c = (tid & 15) * 4;      // k 0..60
    int b_r = tid >> 4;            // k-row 0..15, 4 passes of +16
    int b_c = (tid & 15) * 4;      // n 0..60

    for (int kt = 0; kt < K; kt += BK) {
        // ---- A tile: [BM][BK] f32 -> bf16 ----
#pragma unroll
        for (int p = 0; p < 8; p++) {
            int r = a_r + p * 16;
            int grow = row0 + r;
            float4 v = make_float4(0.f, 0.f, 0.f, 0.f);
            if (grow < n) v = *(const float4*)(A + (size_t)grow * K + kt + a_c);
            uint2 u;
            u.x = bf2_pack(v.x, v.y);
            u.y = bf2_pack(v.z, v.w);
            *(uint2*)&As[r][a_c] = u;
        }
        // ---- B tile: [BK][BN] f32 -> bf16, transposed into k-pair packing ----
#pragma unroll
        for (int p = 0; p < 4; p++) {
            int kr = b_r + p * 16;
            float4 v = *(const float4*)(B + (size_t)(kt + kr) * M + col0 + b_c);
            int kp = kr >> 1, hi = kr & 1;
            ((__nv_bfloat16*)&Bs[kp][b_c + 0])[hi] = __float2bfloat16_rn(v.x);
            ((__nv_bfloat16*)&Bs[kp][b_c + 1])[hi] = __float2bfloat16_rn(v.y);
            ((__nv_bfloat16*)&Bs[kp][b_c + 2])[hi] = __float2bfloat16_rn(v.z);
            ((__nv_bfloat16*)&Bs[kp][b_c + 3])[hi] = __float2bfloat16_rn(v.w);
        }
        __syncthreads();
#pragma unroll
        for (int kk = 0; kk < BK; kk += 16) {
            uint32_t afr[2][4];
#pragma unroll
            for (int t = 0; t < 2; t++) {
                int m = warpM * 32 + t * 16 + gid;
                int k0 = kk + 2 * tig;
                afr[t][0] = *(const uint32_t*)&As[m][k0];
                afr[t][1] = *(const uint32_t*)&As[m + 8][k0];
                afr[t][2] = *(const uint32_t*)&As[m][k0 + 8];
                afr[t][3] = *(const uint32_t*)&As[m + 8][k0 + 8];
            }
            uint32_t bfr[4][2];
#pragma unroll
            for (int t = 0; t < 4; t++) {
                int nn2 = warpN * 32 + t * 8 + gid;
                int kp0 = (kk >> 1) + tig;
                bfr[t][0] = Bs[kp0][nn2];
                bfr[t][1] = Bs[kp0 + 4][nn2];
            }
#pragma unroll
            for (int i = 0; i < 2; i++)
#pragma unroll
                for (int j = 0; j < 4; j++)
                    mma_bf16(c[i][j], afr[i], bfr[j]);
        }
        __syncthreads();
    }

    // ---- epilogue: bf16 store + fused attention partial dots ----
    int h = col0 / HIDC;
    int inh0 = col0 - h * HIDC;
    float ws[4][2], wd[4][2];
#pragma unroll
    for (int j = 0; j < 4; j++)
#pragma unroll
        for (int q = 0; q < 2; q++) {
            int cc = inh0 + warpN * 32 + j * 8 + tig * 2 + q;
            ws[j][q] = a_s[h * HIDC + cc];
            wd[j][q] = a_d[h * HIDC + cc];
        }
#pragma unroll
    for (int i = 0; i < 2; i++) {
        int r0 = row0 + warpM * 32 + i * 16 + gid;
        float ps0 = 0.f, pd0 = 0.f, ps8 = 0.f, pd8 = 0.f;
#pragma unroll
        for (int j = 0; j < 4; j++) {
            ps0 += c[i][j][0] * ws[j][0] + c[i][j][1] * ws[j][1];
            pd0 += c[i][j][0] * wd[j][0] + c[i][j][1] * wd[j][1];
            ps8 += c[i][j][2] * ws[j][0] + c[i][j][3] * ws[j][1];
            pd8 += c[i][j][2] * wd[j][0] + c[i][j][3] * wd[j][1];
            int cc = col0 + warpN * 32 + j * 8 + tig * 2;
            if (r0 < n) {
                __nv_bfloat162 v = __float22bfloat162_rn(make_float2(c[i][j][0], c[i][j][1]));
                *(__nv_bfloat162*)(xlh + (size_t)r0 * M + cc) = v;
            }
            if (r0 + 8 < n) {
                __nv_bfloat162 v = __float22bfloat162_rn(make_float2(c[i][j][2], c[i][j][3]));
                *(__nv_bfloat162*)(xlh + (size_t)(r0 + 8) * M + cc) = v;
            }
        }
#pragma unroll
        for (int o = 1; o < 4; o <<= 1) {
            ps0 += __shfl_xor_sync(0xffffffffu, ps0, o);
            pd0 += __shfl_xor_sync(0xffffffffu, pd0, o);
            ps8 += __shfl_xor_sync(0xffffffffu, ps8, o);
            pd8 += __shfl_xor_sync(0xffffffffu, pd8, o);
        }
        if (tig == 0) {
            if (r0 < n) {
                atomicAdd(&as[r0 * H + h], ps0);
                atomicAdd(&ad[r0 * H + h], pd0);
            }
            if (r0 + 8 < n) {
                atomicAdd(&as[(r0 + 8) * H + h], ps8);
                atomicAdd(&ad[(r0 + 8) * H + h], pd8);
            }
        }
    }
}

// ==================== fused softmax + bf16 gather aggregate =================
// one warp per (node, head); lane handles channels 4*lane..4*lane+3 (uint2 gather)
__global__ void k_node_agg(const int* __restrict__ csr_src,
                           const int* __restrict__ row_ptr,
                           const __nv_bfloat16* __restrict__ xlh,
                           const float* __restrict__ as,
                           const float* __restrict__ ad,
                           const float* __restrict__ b,
                           float* __restrict__ out,
                           int n, int H, int M, int relu) {
    int w = (blockIdx.x * blockDim.x + threadIdx.x) >> 5;
    if (w >= n * H) return;
    int node = w / H, h = w - node * H;
    int lane = threadIdx.x & 31;
    int beg = row_ptr[node], deg = row_ptr[node + 1] - beg;
    float ad_n = ad[node * H + h];

    float m = -3.4e38f;
    for (int i = lane; i < deg; i += 32) {
        int s = csr_src[beg + i];
        float e = as[s * H + h] + ad_n;
        e = e > 0.f ? e : 0.2f * e;
        m = fmaxf(m, e);
    }
#pragma unroll
    for (int o = 16; o; o >>= 1) m = fmaxf(m, __shfl_xor_sync(0xffffffffu, m, o));

    float den = 0.f;
    float a00 = 0.f, a01 = 0.f, a10 = 0.f, a11 = 0.f;
    const uint32_t* xbase = (const uint32_t*)xlh;
    for (int i0 = 0; i0 < deg; i0 += 32) {
        int i = i0 + lane;
        float x = 0.f; int s = 0;
        if (i < deg) {
            s = csr_src[beg + i];
            float e = as[s * H + h] + ad_n;
            e = e > 0.f ? e : 0.2f * e;
            x = __expf(e - m);
            den += x;
        }
        int cnt = min(32, deg - i0);
        for (int j = 0; j < cnt; j++) {
            float xj = __shfl_sync(0xffffffffu, x, j);
            int   sj = __shfl_sync(0xffffffffu, s, j);
            const uint2 u = *(const uint2*)(xbase + (((size_t)sj * M + h * HIDC) >> 1) + 2 * lane);
            a00 += xj * __uint_as_float(u.x << 16);
            a01 += xj * __uint_as_float(u.x & 0xffff0000u);
            a10 += xj * __uint_as_float(u.y << 16);
            a11 += xj * __uint_as_float(u.y & 0xffff0000u);
        }
    }
#pragma unroll
    for (int o = 16; o; o >>= 1) den += __shfl_xor_sync(0xffffffffu, den, o);
    float inv = 1.f / den;

    int c0 = 4 * lane;
    float v0 = a00 * inv + b[h * HIDC + c0];
    float v1 = a01 * inv + b[h * HIDC + c0 + 1];
    float v2 = a10 * inv + b[h * HIDC + c0 + 2];
    float v3 = a11 * inv + b[h * HIDC + c0 + 3];
    if (relu) {
        v0 = fmaxf(v0, 0.f); v1 = fmaxf(v1, 0.f);
        v2 = fmaxf(v2, 0.f); v3 = fmaxf(v3, 0.f);
    }
    float* op = out + (size_t)node * M + h * HIDC;
    *(float4*)(op + c0) = make_float4(v0, v1, v2, v3);
}

// ==================== pool + MLP ============================================
__global__ void k_pool(const float* __restrict__ h, float* __restrict__ pool, int n) {
    int t = threadIdx.x;  // 128
    float s = 0.f;
    for (int r = blockIdx.x; r < n; r += gridDim.x)
        s += h[(size_t)r * HIDC + t];
    atomicAdd(&pool[t], s);
}
__global__ void k_mlp(const float* __restrict__ pool, const float* __restrict__ Wm1,
                      const float* __restrict__ bm1, const float* __restrict__ Wm2,
                      const float* __restrict__ bm2, float* __restrict__ out,
                      float invn) {
    __shared__ float g[HIDC];
    __shared__ float t1[HIDC / 2];
    int t = threadIdx.x;  // 128
    g[t] = pool[t] * invn;
    __syncthreads();
    if (t < HIDC / 2) {
        float s = bm1[t];
#pragma unroll 8
        for (int i = 0; i < HIDC; i++) s += g[i] * Wm1[i * (HIDC / 2) + t];
        t1[t] = fmaxf(s, 0.f);
    }
    __syncthreads();
    if (t == 0) {
        float s = bm2[0];
#pragma unroll 8
        for (int j = 0; j < HIDC / 2; j++) s += t1[j] * Wm2[j];
        out[0] = s;
    }
}

// ============================================================================
extern "C" void kernel_launch(void* const* d_in, const int* in_sizes, int n_in,
                              void* d_out, int out_size) {
    const float* x    = (const float*)d_in[0];
    const int*   ei   = (const int*)  d_in[1];
    const float* W0   = (const float*)d_in[2];
    const float* as0  = (const float*)d_in[3];
    const float* ad0  = (const float*)d_in[4];
    const float* b0   = (const float*)d_in[5];
    const float* W1   = (const float*)d_in[6];
    const float* as1  = (const float*)d_in[7];
    const float* ad1  = (const float*)d_in[8];
    const float* b1   = (const float*)d_in[9];
    const float* W2   = (const float*)d_in[10];
    const float* as2  = (const float*)d_in[11];
    const float* ad2  = (const float*)d_in[12];
    const float* b2   = (const float*)d_in[13];
    const float* Wm1  = (const float*)d_in[14];
    const float* bm1  = (const float*)d_in[15];
    const float* Wm2  = (const float*)d_in[16];
    const float* bm2  = (const float*)d_in[17];

    int n = in_sizes[0] / DIN;        // 20000
    int E = in_sizes[1] / 2;          // 320000
    int Etot = E + n;

    float *h1, *h2, *asb, *adb, *pool;
    __nv_bfloat16* xlh;
    int *csr_src, *row_ptr, *cnt, *cursor;
    { void* p;
      cudaGetSymbolAddress(&p, g_h1);      h1      = (float*)p;
      cudaGetSymbolAddress(&p, g_h2);      h2      = (float*)p;
      cudaGetSymbolAddress(&p, g_xlh);     xlh     = (__nv_bfloat16*)p;
      cudaGetSymbolAddress(&p, g_as);      asb     = (float*)p;
      cudaGetSymbolAddress(&p, g_ad);      adb     = (float*)p;
      cudaGetSymbolAddress(&p, g_pool);    pool    = (float*)p;
      cudaGetSymbolAddress(&p, g_csr_src); csr_src = (int*)p;
      cudaGetSymbolAddress(&p, g_row_ptr); row_ptr = (int*)p;
      cudaGetSymbolAddress(&p, g_cnt);     cnt     = (int*)p;
      cudaGetSymbolAddress(&p, g_cursor);  cursor  = (int*)p;
    }

    int initN = 3 * n * NHEADS;       // 240000 covers everything
    k_init   <<<(initN + 255) / 256, 256>>>(cnt, asb, adb, pool, n);
    k_count  <<<(Etot + 255) / 256, 256>>>(ei, E, Etot, cnt);
    k_scan   <<<1, 1024>>>(cnt, row_ptr, cursor, n);
    k_scatter<<<(Etot + 255) / 256, 256>>>(ei, E, Etot, cursor, csr_src);

    auto run_layer = [&](const float* in, int K, int H, int layer,
                         const float* W, const float* a_s, const float* a_d,
                         const float* b, float* out, int relu) {
        int M = H * HIDC;
        float* asL = asb + (size_t)layer * NN * NHEADS;
        float* adL = adb + (size_t)layer * NN * NHEADS;
        dim3 gg(M / BN, (n + BM - 1) / BM);
        k_gemm_fused<<<gg, 256>>>(in, W, a_s, a_d, xlh, asL, adL, n, K, M, H);
        int warps = n * H;
        k_node_agg<<<(warps * 32 + 255) / 256, 256>>>(csr_src, row_ptr, xlh,
                                                      asL, adL, b, out, n, H, M, relu);
    };

    run_layer(x,  DIN,         NHEADS, 0, W0, as0, ad0, b0, h1, 1);
    run_layer(h1, NHEADS*HIDC, NHEADS, 1, W1, as1, ad1, b1, h2, 1);
    run_layer(h2, NHEADS*HIDC, 1,      2, W2, as2, ad2, b2, h1, 0);

    k_pool<<<256, HIDC>>>(h1, pool, n);
    k_mlp<<<1, HIDC>>>(pool, Wm1, bm1, Wm2, bm2, (float*)d_out, 1.f / (float)n);
}

// round 12
// speedup vs baseline: 1.3508x; 1.1403x over previous
#include <cuda_runtime.h>
#include <cuda_bf16.h>
#include <cstdint>

#define NN 20000
#define DIN 128
#define HIDC 128
#define NHEADS 4
#define MAXM (NHEADS * HIDC)      // 512
#define EMAX 320000
#define ETOTMAX (EMAX + NN)

// -------------------- scratch (device globals) ------------------------------
__device__ float         g_h1 [NN * MAXM];            // f32 (final layer out)
__device__ __nv_bfloat16 g_hb0[NN * MAXM];            // bf16 layer outputs
__device__ __nv_bfloat16 g_hb1[NN * MAXM];
__device__ __nv_bfloat16 g_xb [NN * DIN];             // bf16 input x
__device__ uint32_t      g_wpk[196608];               // packed bf16 weights
__device__ __nv_bfloat16 g_xlh[NN * MAXM];
__device__ float         g_as [3 * NN * NHEADS];
__device__ float         g_ad [3 * NN * NHEADS];
__device__ float         g_pool[HIDC];
__device__ int           g_csr_src[ETOTMAX];
__device__ int           g_row_ptr[NN + 1];
__device__ int           g_cnt[NN];
__device__ int           g_cursor[NN];

// -------------------- helpers ----------------------------------------------
__device__ __forceinline__ uint32_t bf2_pack(float lo, float hi) {
    __nv_bfloat162 v = __float22bfloat162_rn(make_float2(lo, hi));
    return *(uint32_t*)&v;
}
__device__ __forceinline__ uint32_t smem_u32(const void* p) {
    return (uint32_t)__cvta_generic_to_shared(p);
}
__device__ __forceinline__ void cp16(uint32_t saddr, const void* g, int srcsz) {
    asm volatile("cp.async.cg.shared.global [%0], [%1], 16, %2;"
                 :: "r"(saddr), "l"(g), "r"(srcsz));
}
__device__ __forceinline__ void cp_commit() {
    asm volatile("cp.async.commit_group;");
}
template <int N> __device__ __forceinline__ void cp_wait() {
    asm volatile("cp.async.wait_group %0;" :: "n"(N));
}
__device__ __forceinline__ void edge_sd(const int* __restrict__ ei, int E, int e,
                                        int& s, int& d) {
    if (e < E) { s = ei[e]; d = ei[E + e]; }
    else       { s = d = e - E; }
}

// ==================== conversions ===========================================
__global__ void k_cvt_x(const float* __restrict__ x, uint32_t* __restrict__ xb,
                        int n2) {
    int i = blockIdx.x * blockDim.x + threadIdx.x;
    if (i < n2) xb[i] = bf2_pack(x[2 * i], x[2 * i + 1]);
}
// W[K,M] f32 -> Wpk[K/2, M] u32 (bf16 pair of k, k+1 per column m)
__global__ void k_cvt_w(const float* __restrict__ W, uint32_t* __restrict__ Wpk,
                        int M, int tot) {
    int i = blockIdx.x * blockDim.x + threadIdx.x;
    if (i >= tot) return;
    int kp = i / M, m = i - kp * M;
    Wpk[i] = bf2_pack(W[(2 * kp) * M + m], W[(2 * kp + 1) * M + m]);
}

// ==================== init (cnt, as/ad x3, pool) ============================
__global__ void k_init(int* cnt, float* as, float* ad, float* pool, int n) {
    int i = blockIdx.x * blockDim.x + threadIdx.x;
    if (i < n) cnt[i] = 0;
    int tot = 3 * n * NHEADS;
    if (i < tot) { as[i] = 0.f; ad[i] = 0.f; }
    if (i < HIDC) pool[i] = 0.f;
}

// ==================== CSR build =============================================
__global__ void k_count(const int* __restrict__ ei, int E, int Etot,
                        int* __restrict__ cnt) {
    int e = blockIdx.x * blockDim.x + threadIdx.x;
    if (e >= Etot) return;
    int s, d; edge_sd(ei, E, e, s, d);
    atomicAdd(&cnt[d], 1);
}
__global__ void k_scan(const int* __restrict__ cnt, int* __restrict__ row_ptr,
                       int* __restrict__ cursor, int n) {
    __shared__ int part[1024];
    int t = threadIdx.x;
    int per = (n + 1023) / 1024;
    int begi = t * per;
    int endi = min(n, begi + per);
    int s = 0;
    for (int i = begi; i < endi; i++) s += cnt[i];
    part[t] = s;
    __syncthreads();
    for (int o = 1; o < 1024; o <<= 1) {
        int v = (t >= o) ? part[t - o] : 0;
        __syncthreads();
        part[t] += v;
        __syncthreads();
    }
    int off = t ? part[t - 1] : 0;
    for (int i = begi; i < endi; i++) {
        row_ptr[i] = off; cursor[i] = off;
        off += cnt[i];
    }
    if (t == 1023) row_ptr[n] = part[1023];
}
__global__ void k_scatter(const int* __restrict__ ei, int E, int Etot,
                          int* __restrict__ cursor, int* __restrict__ csr_src) {
    int e = blockIdx.x * blockDim.x + threadIdx.x;
    if (e >= Etot) return;
    int s, d; edge_sd(ei, E, e, s, d);
    int pos = atomicAdd(&cursor[d], 1);
    csr_src[pos] = s;
}

// ==================== cp.async bf16 GEMM + attn-dot epilogue ================
// C = A[n,K](bf16) @ Wpk[K/2,M](packed bf16), mma.m16n8k16, fp32 accum.
// BM=128, BN=64, BK=64, 256 threads, 2-stage cp.async double buffer.
#define BM 128
#define BN 64
#define BK 64
#define AS_STRIDE (BK + 8)                 // bf16 units (72) -> 144 B/row
#define BS_STRIDE (BN + 8)                 // u32 units (72)  -> 288 B/row
#define AS_BYTES (BM * AS_STRIDE * 2)      // 18432
#define BS_BYTES ((BK / 2) * BS_STRIDE * 4) // 9216
#define STAGE_BYTES (AS_BYTES + BS_BYTES)
#define SMEM_BYTES (2 * STAGE_BYTES)       // 55296

__device__ __forceinline__ void mma_bf16(float* c, const uint32_t* a, const uint32_t* b) {
    asm volatile(
        "mma.sync.aligned.m16n8k16.row.col.f32.bf16.bf16.f32 "
        "{%0,%1,%2,%3}, {%4,%5,%6,%7}, {%8,%9}, {%0,%1,%2,%3};"
        : "+f"(c[0]), "+f"(c[1]), "+f"(c[2]), "+f"(c[3])
        : "r"(a[0]), "r"(a[1]), "r"(a[2]), "r"(a[3]), "r"(b[0]), "r"(b[1]));
}

__global__ __launch_bounds__(256) void k_gemm_fused(
    const __nv_bfloat16* __restrict__ A, const uint32_t* __restrict__ Wpk,
    const float* __restrict__ a_s, const float* __restrict__ a_d,
    __nv_bfloat16* __restrict__ xlh,
    float* __restrict__ as, float* __restrict__ ad,
    int n, int K, int M, int H) {
    extern __shared__ char smem[];
    int tid = threadIdx.x;
    int warp = tid >> 5, lane = tid & 31;
    int gid = lane >> 2, tig = lane & 3;
    int warpM = warp & 3, warpN = warp >> 2;
    int row0 = blockIdx.y * BM, col0 = blockIdx.x * BN;

    float c[2][4][4] = {};

    // copy assignments
    int a_r = tid >> 3;            // 0..31 (+32 per pass, 4 passes)
    int a_c = (tid & 7) * 8;       // bf16 k-offset, 16B chunks
    int b_r = tid >> 4;            // 0..15 (+16, 2 passes)
    int b_c = (tid & 15) * 4;      // u32 n-offset, 16B chunks

    auto issue = [&](int kt, int st) {
        char* base = smem + st * STAGE_BYTES;
#pragma unroll
        for (int p = 0; p < 4; p++) {
            int r = a_r + p * 32;
            int grow = row0 + r;
            int sz = (grow < n) ? 16 : 0;
            const __nv_bfloat16* gA = A + (size_t)grow * K + kt + a_c;
            cp16(smem_u32(base + r * (AS_STRIDE * 2) + a_c * 2), gA, sz);
        }
        char* bbase = base + AS_BYTES;
        int ktp = kt >> 1;
#pragma unroll
        for (int p = 0; p < 2; p++) {
            int r = b_r + p * 16;
            const uint32_t* gB = Wpk + (size_t)(ktp + r) * M + col0 + b_c;
            cp16(smem_u32(bbase + r * (BS_STRIDE * 4) + b_c * 4), gB, 16);
        }
    };

    auto compute = [&](int st) {
        const __nv_bfloat16* As = (const __nv_bfloat16*)(smem + st * STAGE_BYTES);
        const uint32_t* Bs = (const uint32_t*)(smem + st * STAGE_BYTES + AS_BYTES);
#pragma unroll
        for (int kk = 0; kk < BK; kk += 16) {
            uint32_t afr[2][4];
#pragma unroll
            for (int t = 0; t < 2; t++) {
                int m = warpM * 32 + t * 16 + gid;
                int k0 = kk + 2 * tig;
                const __nv_bfloat16* rm = As + m * AS_STRIDE;
                const __nv_bfloat16* rm8 = As + (m + 8) * AS_STRIDE;
                afr[t][0] = *(const uint32_t*)(rm + k0);
                afr[t][1] = *(const uint32_t*)(rm8 + k0);
                afr[t][2] = *(const uint32_t*)(rm + k0 + 8);
                afr[t][3] = *(const uint32_t*)(rm8 + k0 + 8);
            }
            uint32_t bfr[4][2];
            int kp0 = (kk >> 1) + tig;
#pragma unroll
            for (int t = 0; t < 4; t++) {
                int nn2 = warpN * 32 + t * 8 + gid;
                bfr[t][0] = Bs[kp0 * BS_STRIDE + nn2];
                bfr[t][1] = Bs[(kp0 + 4) * BS_STRIDE + nn2];
            }
#pragma unroll
            for (int i = 0; i < 2; i++)
#pragma unroll
                for (int j = 0; j < 4; j++)
                    mma_bf16(c[i][j], afr[i], bfr[j]);
        }
    };

    int KT = K / BK;
    issue(0, 0);
    cp_commit();
    for (int t = 0; t < KT; t++) {
        int st = t & 1;
        if (t + 1 < KT) {
            issue((t + 1) * BK, st ^ 1);
            cp_commit();
            cp_wait<1>();
        } else {
            cp_wait<0>();
        }
        __syncthreads();
        compute(st);
        __syncthreads();
    }

    // ---- epilogue: bf16 store + fused attention partial dots ----
    int h = col0 / HIDC;
    int inh0 = col0 - h * HIDC;
    float ws[4][2], wd[4][2];
#pragma unroll
    for (int j = 0; j < 4; j++)
#pragma unroll
        for (int q = 0; q < 2; q++) {
            int cc = inh0 + warpN * 32 + j * 8 + tig * 2 + q;
            ws[j][q] = a_s[h * HIDC + cc];
            wd[j][q] = a_d[h * HIDC + cc];
        }
#pragma unroll
    for (int i = 0; i < 2; i++) {
        int r0 = row0 + warpM * 32 + i * 16 + gid;
        float ps0 = 0.f, pd0 = 0.f, ps8 = 0.f, pd8 = 0.f;
#pragma unroll
        for (int j = 0; j < 4; j++) {
            ps0 += c[i][j][0] * ws[j][0] + c[i][j][1] * ws[j][1];
            pd0 += c[i][j][0] * wd[j][0] + c[i][j][1] * wd[j][1];
            ps8 += c[i][j][2] * ws[j][0] + c[i][j][3] * ws[j][1];
            pd8 += c[i][j][2] * wd[j][0] + c[i][j][3] * wd[j][1];
            int cc = col0 + warpN * 32 + j * 8 + tig * 2;
            if (r0 < n) {
                __nv_bfloat162 v = __float22bfloat162_rn(make_float2(c[i][j][0], c[i][j][1]));
                *(__nv_bfloat162*)(xlh + (size_t)r0 * M + cc) = v;
            }
            if (r0 + 8 < n) {
                __nv_bfloat162 v = __float22bfloat162_rn(make_float2(c[i][j][2], c[i][j][3]));
                *(__nv_bfloat162*)(xlh + (size_t)(r0 + 8) * M + cc) = v;
            }
        }
#pragma unroll
        for (int o = 1; o < 4; o <<= 1) {
            ps0 += __shfl_xor_sync(0xffffffffu, ps0, o);
            pd0 += __shfl_xor_sync(0xffffffffu, pd0, o);
            ps8 += __shfl_xor_sync(0xffffffffu, ps8, o);
            pd8 += __shfl_xor_sync(0xffffffffu, pd8, o);
        }
        if (tig == 0) {
            if (r0 < n) {
                atomicAdd(&as[r0 * H + h], ps0);
                atomicAdd(&ad[r0 * H + h], pd0);
            }
            if (r0 + 8 < n) {
                atomicAdd(&as[(r0 + 8) * H + h], ps8);
                atomicAdd(&ad[(r0 + 8) * H + h], pd8);
            }
        }
    }
}

// ==================== fused softmax + bf16 gather aggregate =================
// one warp per (node, head); lane handles channels 4*lane..4*lane+3.
// outb != null -> packed bf16 output; else f32 to outf.
__global__ void k_node_agg(const int* __restrict__ csr_src,
                           const int* __restrict__ row_ptr,
                           const __nv_bfloat16* __restrict__ xlh,
                           const float* __restrict__ as,
                           const float* __restrict__ ad,
                           const float* __restrict__ b,
                           float* __restrict__ outf,
                           uint32_t* __restrict__ outb,
                           int n, int H, int M, int relu) {
    int w = (blockIdx.x * blockDim.x + threadIdx.x) >> 5;
    if (w >= n * H) return;
    int node = w / H, h = w - node * H;
    int lane = threadIdx.x & 31;
    int beg = row_ptr[node], deg = row_ptr[node + 1] - beg;
    float ad_n = ad[node * H + h];

    float m = -3.4e38f;
    for (int i = lane; i < deg; i += 32) {
        int s = csr_src[beg + i];
        float e = as[s * H + h] + ad_n;
        e = e > 0.f ? e : 0.2f * e;
        m = fmaxf(m, e);
    }
#pragma unroll
    for (int o = 16; o; o >>= 1) m = fmaxf(m, __shfl_xor_sync(0xffffffffu, m, o));

    float den = 0.f;
    float a00 = 0.f, a01 = 0.f, a10 = 0.f, a11 = 0.f;
    const uint32_t* xbase = (const uint32_t*)xlh;
    for (int i0 = 0; i0 < deg; i0 += 32) {
        int i = i0 + lane;
        float x = 0.f; int s = 0;
        if (i < deg) {
            s = csr_src[beg + i];
            float e = as[s * H + h] + ad_n;
            e = e > 0.f ? e : 0.2f * e;
            x = __expf(e - m);
            den += x;
        }
        int cnt = min(32, deg - i0);
        for (int j = 0; j < cnt; j++) {
            float xj = __shfl_sync(0xffffffffu, x, j);
            int   sj = __shfl_sync(0xffffffffu, s, j);
            const uint2 u = *(const uint2*)(xbase + (((size_t)sj * M + h * HIDC) >> 1) + 2 * lane);
            a00 += xj * __uint_as_float(u.x << 16);
            a01 += xj * __uint_as_float(u.x & 0xffff0000u);
            a10 += xj * __uint_as_float(u.y << 16);
            a11 += xj * __uint_as_float(u.y & 0xffff0000u);
        }
    }
#pragma unroll
    for (int o = 16; o; o >>= 1) den += __shfl_xor_sync(0xffffffffu, den, o);
    float inv = 1.f / den;

    int c0 = 4 * lane;
    float v0 = a00 * inv + b[h * HIDC + c0];
    float v1 = a01 * inv + b[h * HIDC + c0 + 1];
    float v2 = a10 * inv + b[h * HIDC + c0 + 2];
    float v3 = a11 * inv + b[h * HIDC + c0 + 3];
    if (relu) {
        v0 = fmaxf(v0, 0.f); v1 = fmaxf(v1, 0.f);
        v2 = fmaxf(v2, 0.f); v3 = fmaxf(v3, 0.f);
    }
    size_t base = (size_t)node * M + h * HIDC + c0;
    if (outb) {
        uint2 o2;
        o2.x = bf2_pack(v0, v1);
        o2.y = bf2_pack(v2, v3);
        *(uint2*)(outb + (base >> 1)) = o2;
    } else {
        *(float4*)(outf + base) = make_float4(v0, v1, v2, v3);
    }
}

// ==================== pool + MLP ============================================
__global__ void k_pool(const float* __restrict__ h, float* __restrict__ pool, int n) {
    int t = threadIdx.x;  // 128
    float s = 0.f;
    for (int r = blockIdx.x; r < n; r += gridDim.x)
        s += h[(size_t)r * HIDC + t];
    atomicAdd(&pool[t], s);
}
__global__ void k_mlp(const float* __restrict__ pool, const float* __restrict__ Wm1,
                      const float* __restrict__ bm1, const float* __restrict__ Wm2,
                      const float* __restrict__ bm2, float* __restrict__ out,
                      float invn) {
    __shared__ float g[HIDC];
    __shared__ float t1[HIDC / 2];
    int t = threadIdx.x;  // 128
    g[t] = pool[t] * invn;
    __syncthreads();
    if (t < HIDC / 2) {
        float s = bm1[t];
#pragma unroll 8
        for (int i = 0; i < HIDC; i++) s += g[i] * Wm1[i * (HIDC / 2) + t];
        t1[t] = fmaxf(s, 0.f);
    }
    __syncthreads();
    if (t == 0) {
        float s = bm2[0];
#pragma unroll 8
        for (int j = 0; j < HIDC / 2; j++) s += t1[j] * Wm2[j];
        out[0] = s;
    }
}

// ============================================================================
extern "C" void kernel_launch(void* const* d_in, const int* in_sizes, int n_in,
                              void* d_out, int out_size) {
    const float* x    = (const float*)d_in[0];
    const int*   ei   = (const int*)  d_in[1];
    const float* W0   = (const float*)d_in[2];
    const float* as0  = (const float*)d_in[3];
    const float* ad0  = (const float*)d_in[4];
    const float* b0   = (const float*)d_in[5];
    const float* W1   = (const float*)d_in[6];
    const float* as1  = (const float*)d_in[7];
    const float* ad1  = (const float*)d_in[8];
    const float* b1   = (const float*)d_in[9];
    const float* W2   = (const float*)d_in[10];
    const float* as2  = (const float*)d_in[11];
    const float* ad2  = (const float*)d_in[12];
    const float* b2   = (const float*)d_in[13];
    const float* Wm1  = (const float*)d_in[14];
    const float* bm1  = (const float*)d_in[15];
    const float* Wm2  = (const float*)d_in[16];
    const float* bm2  = (const float*)d_in[17];

    int n = in_sizes[0] / DIN;        // 20000
    int E = in_sizes[1] / 2;          // 320000
    int Etot = E + n;

    float *h1, *asb, *adb, *pool;
    __nv_bfloat16 *xlh, *hb0, *hb1, *xb;
    uint32_t* wpk;
    int *csr_src, *row_ptr, *cnt, *cursor;
    { void* p;
      cudaGetSymbolAddress(&p, g_h1);      h1      = (float*)p;
      cudaGetSymbolAddress(&p, g_hb0);     hb0     = (__nv_bfloat16*)p;
      cudaGetSymbolAddress(&p, g_hb1);     hb1     = (__nv_bfloat16*)p;
      cudaGetSymbolAddress(&p, g_xb);      xb      = (__nv_bfloat16*)p;
      cudaGetSymbolAddress(&p, g_wpk);     wpk     = (uint32_t*)p;
      cudaGetSymbolAddress(&p, g_xlh);     xlh     = (__nv_bfloat16*)p;
      cudaGetSymbolAddress(&p, g_as);      asb     = (float*)p;
      cudaGetSymbolAddress(&p, g_ad);      adb     = (float*)p;
      cudaGetSymbolAddress(&p, g_pool);    pool    = (float*)p;
      cudaGetSymbolAddress(&p, g_csr_src); csr_src = (int*)p;
      cudaGetSymbolAddress(&p, g_row_ptr); row_ptr = (int*)p;
      cudaGetSymbolAddress(&p, g_cnt);     cnt     = (int*)p;
      cudaGetSymbolAddress(&p, g_cursor);  cursor  = (int*)p;
    }

    static bool attr_done = false;
    if (!attr_done) {
        cudaFuncSetAttribute(k_gemm_fused,
                             cudaFuncAttributeMaxDynamicSharedMemorySize, SMEM_BYTES);
        attr_done = true;
    }

    // ---- conversions (per launch; deterministic) ----
    uint32_t* w0p = wpk;                       // 64*512
    uint32_t* w1p = wpk + 32768;               // 256*512
    uint32_t* w2p = w1p + 131072;              // 256*128
    {
        int n2 = n * DIN / 2;
        k_cvt_x<<<(n2 + 255) / 256, 256>>>(x, (uint32_t*)xb, n2);
        int t0 = 64 * 512, t1 = 256 * 512, t2 = 256 * 128;
        k_cvt_w<<<(t0 + 255) / 256, 256>>>(W0, w0p, 512, t0);
        k_cvt_w<<<(t1 + 255) / 256, 256>>>(W1, w1p, 512, t1);
        k_cvt_w<<<(t2 + 255) / 256, 256>>>(W2, w2p, 128, t2);
    }

    int initN = 3 * n * NHEADS;
    k_init   <<<(initN + 255) / 256, 256>>>(cnt, asb, adb, pool, n);
    k_count  <<<(Etot + 255) / 256, 256>>>(ei, E, Etot, cnt);
    k_scan   <<<1, 1024>>>(cnt, row_ptr, cursor, n);
    k_scatter<<<(Etot + 255) / 256, 256>>>(ei, E, Etot, cursor, csr_src);

    auto run_layer = [&](const __nv_bfloat16* in, const uint32_t* Wp, int K, int H,
                         int layer, const float* a_s, const float* a_d,
                         const float* b, float* outf, uint32_t* outb, int relu) {
        int M = H * HIDC;
        float* asL = asb + (size_t)layer * NN * NHEADS;
        float* adL = adb + (size_t)layer * NN * NHEADS;
        dim3 gg(M / BN, (n + BM - 1) / BM);
        k_gemm_fused<<<gg, 256, SMEM_BYTES>>>(in, Wp, a_s, a_d, xlh, asL, adL,
                                              n, K, M, H);
        int warps = n * H;
        k_node_agg<<<(warps * 32 + 255) / 256, 256>>>(csr_src, row_ptr, xlh,
                                                      asL, adL, b, outf, outb,
                                                      n, H, M, relu);
    };

    run_layer(xb,  w0p, DIN,         NHEADS, 0, as0, ad0, b0, nullptr, (uint32_t*)hb0, 1);
    run_layer(hb0, w1p, NHEADS*HIDC, NHEADS, 1, as1, ad1, b1, nullptr, (uint32_t*)hb1, 1);
    run_layer(hb1, w2p, NHEADS*HIDC, 1,      2, as2, ad2, b2, h1, nullptr, 0);

    k_pool<<<256, HIDC>>>(h1, pool, n);
    k_mlp<<<1, HIDC>>>(pool, Wm1, bm1, Wm2, bm2, (float*)d_out, 1.f / (float)n);
}